// round 16
// baseline (speedup 1.0000x reference)
#include <cuda_runtime.h>
#include <cuda_bf16.h>
#include <cstdint>

#define NODES 40000
#define EDGES 640000
#define DIM 128
#define GRAPHS 512
#define NEG_SLOPE 0.2f
#define BN_EPS 1e-5f
#define LOG2E 1.4426950408889634f

// ---------------- scratch (no allocations allowed) ----------------
__device__ float d_h0[NODES * DIM];
__device__ float d_xl[NODES * DIM];
__device__ float d_xr[NODES * DIM];
__device__ __nv_bfloat16 d_hhi[NODES * DIM];
__device__ __nv_bfloat16 d_hlo[NODES * DIM];
__device__ __nv_bfloat16 d_whi[3 * 2 * DIM * DIM];
__device__ __nv_bfloat16 d_wlo[3 * 2 * DIM * DIM];
__device__ int d_deg[NODES];
__device__ int d_rowptr[NODES + 1];
__device__ int d_cursor[NODES];
__device__ int d_srcs[EDGES];

__device__ __forceinline__ uint32_t smem_u32(const void* p) {
    uint32_t a;
    asm("{ .reg .u64 t; cvta.to.shared.u64 t, %1; cvt.u32.u64 %0, t; }" : "=r"(a) : "l"(p));
    return a;
}
__device__ __forceinline__ void ldsm_x4(uint32_t* r, uint32_t addr) {
    asm volatile("ldmatrix.sync.aligned.m8n8.x4.shared.b16 {%0,%1,%2,%3}, [%4];"
                 : "=r"(r[0]), "=r"(r[1]), "=r"(r[2]), "=r"(r[3]) : "r"(addr));
}
__device__ __forceinline__ void ldsm_x4_t(uint32_t* r, uint32_t addr) {
    asm volatile("ldmatrix.sync.aligned.m8n8.x4.trans.shared.b16 {%0,%1,%2,%3}, [%4];"
                 : "=r"(r[0]), "=r"(r[1]), "=r"(r[2]), "=r"(r[3]) : "r"(addr));
}
__device__ __forceinline__ void mma16816(float* c, const uint32_t* a, const uint32_t* b) {
    asm volatile(
        "mma.sync.aligned.m16n8k16.row.col.f32.bf16.bf16.f32 "
        "{%0,%1,%2,%3}, {%4,%5,%6,%7}, {%8,%9}, {%0,%1,%2,%3};"
        : "+f"(c[0]), "+f"(c[1]), "+f"(c[2]), "+f"(c[3])
        : "r"(a[0]), "r"(a[1]), "r"(a[2]), "r"(a[3]), "r"(b[0]), "r"(b[1]));
}
__device__ __forceinline__ void cp16(uint32_t saddr, const void* gaddr) {
    asm volatile("cp.async.cg.shared.global [%0], [%1], 16;" :: "r"(saddr), "l"(gaddr));
}
#define CP_COMMIT() asm volatile("cp.async.commit_group;" ::: "memory")
#define CP_WAIT0()  asm volatile("cp.async.wait_group 0;" ::: "memory")
#define CP_WAIT1()  asm volatile("cp.async.wait_group 1;" ::: "memory")

// ---------------- small kernels ----------------
__global__ void k_zero() {
    int i = blockIdx.x * blockDim.x + threadIdx.x;
    if (i < NODES) d_deg[i] = 0;
}
__global__ void k_conv_w(const float* __restrict__ Wl, const float* __restrict__ Wr) {
    int b = blockIdx.x;
    int l = b >> 1, m = b & 1;
    const float* W = (m ? Wr : Wl) + (size_t)l * DIM * DIM;
    __nv_bfloat16* oh = d_whi + (size_t)(l * 2 + m) * DIM * DIM;
    __nv_bfloat16* ol = d_wlo + (size_t)(l * 2 + m) * DIM * DIM;
    for (int t = threadIdx.x; t < DIM * DIM; t += blockDim.x) {
        float v = W[t];
        __nv_bfloat16 h = __float2bfloat16(v);
        oh[t] = h;
        ol[t] = __float2bfloat16(v - __bfloat162float(h));
    }
}
__global__ void k_hist(const int* __restrict__ ei) {
    int e = blockIdx.x * blockDim.x + threadIdx.x;
    if (e < EDGES) atomicAdd(&d_deg[ei[EDGES + e]], 1);
}
#define SCAN_CH 40
__global__ void k_scan() {
    __shared__ int ws[32];
    int t = threadIdx.x, lane = t & 31, wid = t >> 5;
    int base = t * SCAN_CH;
    int s = 0;
    #pragma unroll 4
    for (int k = 0; k < SCAN_CH; k++) {
        int idx = base + k;
        if (idx < NODES) s += d_deg[idx];
    }
    int x = s;
    #pragma unroll
    for (int o = 1; o < 32; o <<= 1) {
        int y = __shfl_up_sync(0xffffffffu, x, o);
        if (lane >= o) x += y;
    }
    if (lane == 31) ws[wid] = x;
    __syncthreads();
    if (wid == 0) {
        int sv = ws[lane], sx = sv;
        #pragma unroll
        for (int o = 1; o < 32; o <<= 1) {
            int y = __shfl_up_sync(0xffffffffu, sx, o);
            if (lane >= o) sx += y;
        }
        ws[lane] = sx - sv;
    }
    __syncthreads();
    int run = ws[wid] + x - s;
    #pragma unroll 4
    for (int k = 0; k < SCAN_CH; k++) {
        int idx = base + k;
        if (idx < NODES) {
            int dg = d_deg[idx];
            d_rowptr[idx] = run;
            d_cursor[idx] = run;
            run += dg;
        }
    }
    if (t == 1023) d_rowptr[NODES] = run;
}
__global__ void k_scatter(const int* __restrict__ ei) {
    int e = blockIdx.x * blockDim.x + threadIdx.x;
    if (e < EDGES) {
        int dst = ei[EDGES + e];
        int pos = atomicAdd(&d_cursor[dst], 1);
        d_srcs[pos] = ei[e];
    }
}

// ---------------- persistent HMMA dual GEMM (bf16 inputs; layers 1-2) ----------------
#define SW_HI 0
#define SW_LO 32768
#define SA_BUF 65536
#define ABUF_SZ 32768
#define GSMEM 131072
#define NTILES (NODES / 64)

__global__ __launch_bounds__(256, 1) void k_gemm_tc(
    const __nv_bfloat16* __restrict__ Ahi, const __nv_bfloat16* __restrict__ Alo,
    const __nv_bfloat16* __restrict__ Whi, const __nv_bfloat16* __restrict__ Wlo,
    const float* __restrict__ bl, const float* __restrict__ br)
{
    extern __shared__ char smem[];
    uint32_t sb = smem_u32(smem);
    int tid = threadIdx.x;
    int mat = blockIdx.y;

    const float* bias = mat ? br : bl;
    float* out = mat ? d_xr : d_xl;
    const uint4* ahi4 = (const uint4*)Ahi;
    const uint4* alo4 = (const uint4*)Alo;
    const uint4* wh4 = (const uint4*)(Whi + (size_t)mat * DIM * DIM);
    const uint4* wl4 = (const uint4*)(Wlo + (size_t)mat * DIM * DIM);

    int tb0 = blockIdx.x;
    for (int t = tid; t < 2048; t += 256) {
        int r = t >> 4, c = t & 15;
        uint32_t so = r * 256 + ((c ^ (r & 7)) << 4);
        cp16(sb + SW_HI + so, wh4 + t);
        cp16(sb + SW_LO + so, wl4 + t);
    }
    if (tb0 < NTILES) {
        int row0 = tb0 * 64;
        for (int t = tid; t < 1024; t += 256) {
            int r = t >> 4, c = t & 15;
            uint32_t so = r * 256 + ((c ^ (r & 7)) << 4);
            cp16(sb + SA_BUF + so, ahi4 + (row0 + r) * 16 + c);
            cp16(sb + SA_BUF + 16384 + so, alo4 + (row0 + r) * 16 + c);
        }
    }
    CP_COMMIT();
    CP_WAIT0();
    __syncthreads();

    int w = tid >> 5, lane = tid & 31;
    int mBase = (w >> 2) * 32;
    int nBase = (w & 3) * 32;
    int arow = lane & 15;
    int asel = lane >> 4;
    int brow_in = (lane & 7) + ((lane >> 3) & 1) * 8;
    int bsel = lane >> 4;
    int r0 = lane >> 2;
    int c2 = (lane & 3) * 2;

    int buf = 0;
    for (int tb = tb0; tb < NTILES; tb += gridDim.x) {
        int tn = tb + gridDim.x;
        if (tn < NTILES) {
            uint32_t ab = sb + SA_BUF + (buf ^ 1) * ABUF_SZ;
            int rown = tn * 64;
            for (int t = tid; t < 1024; t += 256) {
                int r = t >> 4, c = t & 15;
                uint32_t so = r * 256 + ((c ^ (r & 7)) << 4);
                cp16(ab + so, ahi4 + (rown + r) * 16 + c);
                cp16(ab + 16384 + so, alo4 + (rown + r) * 16 + c);
            }
        }
        CP_COMMIT();

        uint32_t sa_hi = sb + SA_BUF + buf * ABUF_SZ;
        uint32_t sa_lo = sa_hi + 16384;

        float acc[2][4][4];
        #pragma unroll
        for (int mt = 0; mt < 2; mt++)
            #pragma unroll
            for (int nt = 0; nt < 4; nt++)
                #pragma unroll
                for (int j = 0; j < 4; j++) acc[mt][nt][j] = 0.f;

        #pragma unroll
        for (int ks = 0; ks < 8; ks++) {
            uint32_t ah[2][4], al[2][4];
            int achunk = ks * 2 + asel;
            #pragma unroll
            for (int mt = 0; mt < 2; mt++) {
                int r = mBase + mt * 16 + arow;
                uint32_t off = r * 256 + ((achunk ^ (r & 7)) << 4);
                ldsm_x4(ah[mt], sa_hi + off);
                ldsm_x4(al[mt], sa_lo + off);
            }
            uint32_t bh[2][4], bo[2][4];
            int brow = ks * 16 + brow_in;
            #pragma unroll
            for (int nt2 = 0; nt2 < 2; nt2++) {
                int chunk = ((nBase + nt2 * 16) >> 3) + bsel;
                uint32_t off = brow * 256 + ((chunk ^ (brow & 7)) << 4);
                ldsm_x4_t(bh[nt2], sb + SW_HI + off);
                ldsm_x4_t(bo[nt2], sb + SW_LO + off);
            }
            #pragma unroll
            for (int mt = 0; mt < 2; mt++)
                #pragma unroll
                for (int nt = 0; nt < 4; nt++) {
                    const uint32_t* ph = &bh[nt >> 1][(nt & 1) * 2];
                    const uint32_t* pl = &bo[nt >> 1][(nt & 1) * 2];
                    mma16816(acc[mt][nt], ah[mt], ph);
                    mma16816(acc[mt][nt], al[mt], ph);
                    mma16816(acc[mt][nt], ah[mt], pl);
                }
        }

        int row0 = tb * 64;
        #pragma unroll
        for (int nt = 0; nt < 4; nt++) {
            int col = nBase + nt * 8 + c2;
            float2 bi = *(const float2*)(bias + col);
            #pragma unroll
            for (int mt = 0; mt < 2; mt++) {
                int g0 = row0 + mBase + mt * 16 + r0;
                float2 o0 = {acc[mt][nt][0] + bi.x, acc[mt][nt][1] + bi.y};
                *(float2*)(out + (size_t)g0 * DIM + col) = o0;
                float2 o1 = {acc[mt][nt][2] + bi.x, acc[mt][nt][3] + bi.y};
                *(float2*)(out + (size_t)(g0 + 8) * DIM + col) = o1;
            }
        }

        CP_WAIT0();
        __syncthreads();
        buf ^= 1;
    }
}

// ---------------- layer-0 GEMM: fp32 x via cp.async pipeline, convert in smem ----------------
#define L0_F32 65536        // 2 x 32768 fp32 A tile
#define L0_BH 131072        // 16384 bf16 hi
#define L0_BL 147456        // 16384 bf16 lo
#define GSMEM_L0 163840

__global__ __launch_bounds__(256, 1) void k_gemm_l0(
    const float* __restrict__ X,
    const __nv_bfloat16* __restrict__ Whi, const __nv_bfloat16* __restrict__ Wlo,
    const float* __restrict__ bl, const float* __restrict__ br)
{
    extern __shared__ char smem[];
    uint32_t sb = smem_u32(smem);
    int tid = threadIdx.x;
    int mat = blockIdx.y;

    const float* bias = mat ? br : bl;
    float* out = mat ? d_xr : d_xl;
    const uint4* wh4 = (const uint4*)(Whi + (size_t)mat * DIM * DIM);
    const uint4* wl4 = (const uint4*)(Wlo + (size_t)mat * DIM * DIM);

    for (int t = tid; t < 2048; t += 256) {
        int r = t >> 4, c = t & 15;
        uint32_t so = r * 256 + ((c ^ (r & 7)) << 4);
        cp16(sb + SW_HI + so, wh4 + t);
        cp16(sb + SW_LO + so, wl4 + t);
    }
    CP_COMMIT();
    int tb0 = blockIdx.x;
    {
        int row0 = tb0 * 64;
        for (int t2 = tid; t2 < 2048; t2 += 256) {
            int r = t2 >> 5, k = t2 & 31;
            cp16(sb + L0_F32 + r * 512 + k * 16, X + (size_t)(row0 + r) * DIM + k * 4);
        }
    }
    CP_COMMIT();

    int w = tid >> 5, lane = tid & 31;
    int mBase = (w >> 2) * 32;
    int nBase = (w & 3) * 32;
    int arow = lane & 15;
    int asel = lane >> 4;
    int brow_in = (lane & 7) + ((lane >> 3) & 1) * 8;
    int bsel = lane >> 4;
    int r0 = lane >> 2;
    int c2 = (lane & 3) * 2;

    int buf = 0;
    for (int tb = tb0; tb < NTILES; tb += gridDim.x) {
        int tn = tb + gridDim.x;
        if (tn < NTILES) {
            int rown = tn * 64;
            uint32_t fb = sb + L0_F32 + (buf ^ 1) * 32768;
            for (int t2 = tid; t2 < 2048; t2 += 256) {
                int r = t2 >> 5, k = t2 & 31;
                cp16(fb + r * 512 + k * 16, X + (size_t)(rown + r) * DIM + k * 4);
            }
            CP_COMMIT();
            CP_WAIT1();
        } else {
            CP_WAIT0();
        }
        __syncthreads();

        const char* f32b = smem + L0_F32 + buf * 32768;
        for (int t = tid; t < 1024; t += 256) {
            int r = t >> 4, c = t & 15;
            float4 f0 = *(const float4*)(f32b + r * 512 + c * 32);
            float4 f1 = *(const float4*)(f32b + r * 512 + c * 32 + 16);
            __nv_bfloat16 h0 = __float2bfloat16(f0.x), h1 = __float2bfloat16(f0.y);
            __nv_bfloat16 h2 = __float2bfloat16(f0.z), h3 = __float2bfloat16(f0.w);
            __nv_bfloat16 h4 = __float2bfloat16(f1.x), h5 = __float2bfloat16(f1.y);
            __nv_bfloat16 h6 = __float2bfloat16(f1.z), h7 = __float2bfloat16(f1.w);
            __nv_bfloat162 hi[4] = {
                __nv_bfloat162(h0, h1), __nv_bfloat162(h2, h3),
                __nv_bfloat162(h4, h5), __nv_bfloat162(h6, h7)};
            __nv_bfloat162 lo[4] = {
                __nv_bfloat162(__float2bfloat16(f0.x - __bfloat162float(h0)),
                               __float2bfloat16(f0.y - __bfloat162float(h1))),
                __nv_bfloat162(__float2bfloat16(f0.z - __bfloat162float(h2)),
                               __float2bfloat16(f0.w - __bfloat162float(h3))),
                __nv_bfloat162(__float2bfloat16(f1.x - __bfloat162float(h4)),
                               __float2bfloat16(f1.y - __bfloat162float(h5))),
                __nv_bfloat162(__float2bfloat16(f1.z - __bfloat162float(h6)),
                               __float2bfloat16(f1.w - __bfloat162float(h7)))};
            uint32_t so = r * 256 + ((c ^ (r & 7)) << 4);
            *(uint4*)(smem + L0_BH + so) = *(uint4*)hi;
            *(uint4*)(smem + L0_BL + so) = *(uint4*)lo;
        }
        __syncthreads();

        float acc[2][4][4];
        #pragma unroll
        for (int mt = 0; mt < 2; mt++)
            #pragma unroll
            for (int nt = 0; nt < 4; nt++)
                #pragma unroll
                for (int j = 0; j < 4; j++) acc[mt][nt][j] = 0.f;

        #pragma unroll
        for (int ks = 0; ks < 8; ks++) {
            uint32_t ah[2][4], al[2][4];
            int achunk = ks * 2 + asel;
            #pragma unroll
            for (int mt = 0; mt < 2; mt++) {
                int r = mBase + mt * 16 + arow;
                uint32_t off = r * 256 + ((achunk ^ (r & 7)) << 4);
                ldsm_x4(ah[mt], sb + L0_BH + off);
                ldsm_x4(al[mt], sb + L0_BL + off);
            }
            uint32_t bh[2][4], bo[2][4];
            int brow = ks * 16 + brow_in;
            #pragma unroll
            for (int nt2 = 0; nt2 < 2; nt2++) {
                int chunk = ((nBase + nt2 * 16) >> 3) + bsel;
                uint32_t off = brow * 256 + ((chunk ^ (brow & 7)) << 4);
                ldsm_x4_t(bh[nt2], sb + SW_HI + off);
                ldsm_x4_t(bo[nt2], sb + SW_LO + off);
            }
            #pragma unroll
            for (int mt = 0; mt < 2; mt++)
                #pragma unroll
                for (int nt = 0; nt < 4; nt++) {
                    const uint32_t* ph = &bh[nt >> 1][(nt & 1) * 2];
                    const uint32_t* pl = &bo[nt >> 1][(nt & 1) * 2];
                    mma16816(acc[mt][nt], ah[mt], ph);
                    mma16816(acc[mt][nt], al[mt], ph);
                    mma16816(acc[mt][nt], ah[mt], pl);
                }
        }

        int row0 = tb * 64;
        #pragma unroll
        for (int nt = 0; nt < 4; nt++) {
            int col = nBase + nt * 8 + c2;
            float2 bi = *(const float2*)(bias + col);
            #pragma unroll
            for (int mt = 0; mt < 2; mt++) {
                int g0 = row0 + mBase + mt * 16 + r0;
                float2 o0 = {acc[mt][nt][0] + bi.x, acc[mt][nt][1] + bi.y};
                *(float2*)(out + (size_t)g0 * DIM + col) = o0;
                float2 o1 = {acc[mt][nt][2] + bi.x, acc[mt][nt][3] + bi.y};
                *(float2*)(out + (size_t)(g0 + 8) * DIM + col) = o1;
            }
        }
        buf ^= 1;
    }
}

// ---------------- GATv2 aggregation: cp.async gather pipeline ----------------
__device__ __forceinline__ float leaky_dot(float4 v, float4 x, float4 w) {
    float zx = v.x + x.x, zy = v.y + x.y, zz = v.z + x.z, zw = v.w + x.w;
    zx = fmaxf(zx, NEG_SLOPE * zx);
    zy = fmaxf(zy, NEG_SLOPE * zy);
    zz = fmaxf(zz, NEG_SLOPE * zz);
    zw = fmaxf(zw, NEG_SLOPE * zw);
    return zx * w.x + zy * w.y + zz * w.z + zw * w.w;
}
__device__ __forceinline__ float hred8(float d) {
    d += __shfl_xor_sync(0xffffffffu, d, 1);
    d += __shfl_xor_sync(0xffffffffu, d, 2);
    d += __shfl_xor_sync(0xffffffffu, d, 4);
    return d;
}
__device__ __forceinline__ float ex2(float x) {
    float r;
    asm("ex2.approx.f32 %0, %1;" : "=f"(r) : "f"(x));
    return r;
}

__global__ __launch_bounds__(256) void k_gat(
    const float* __restrict__ xl, const float* __restrict__ xr,
    const float* __restrict__ att, const float* __restrict__ conv_bias,
    const float* __restrict__ bn_gamma, const float* __restrict__ bn_beta,
    const float* __restrict__ bn_mean, const float* __restrict__ bn_var,
    float* __restrict__ hout, int write_bf, int write_f32)
{
    // per-warp gather buffers: 2 phases x 4 edges x 32 lanes x 16B = 4KB/warp = 32KB/CTA
    __shared__ float4 gsm[8 * 2 * 4 * 32];
    int wid = threadIdx.x >> 5;
    int i = blockIdx.x * 8 + wid;
    if (i >= NODES) return;
    int lane = threadIdx.x & 31;
    int c = lane * 4;
    uint32_t swb = smem_u32(gsm) + wid * 4096 + lane * 16;
    const float4* grd = gsm + wid * 256 + lane;

    float4 w = *(const float4*)(att + c);
    w.x *= LOG2E; w.y *= LOG2E; w.z *= LOG2E; w.w *= LOG2E;
    float4 xr4 = *(const float4*)(xr + (size_t)i * DIM + c);

    float4 xls = *(const float4*)(xl + (size_t)i * DIM + c);
    float m0 = hred8(leaky_dot(xls, xr4, w));
    float denom = 1.0f;
    float4 acc = xls;

    int beg = d_rowptr[i];
    int end = d_rowptr[i + 1];
    int n = end - beg;
    int groups = n >> 2;

    if (groups > 0) {
        #pragma unroll
        for (int e = 0; e < 4; e++) {
            int src = d_srcs[beg + e];
            cp16(swb + e * 512, xl + (size_t)src * DIM + c);
        }
        CP_COMMIT();
    }
    for (int g = 0; g < groups; g++) {
        int ph = g & 1;
        if (g + 1 < groups) {
            int b2 = beg + (g + 1) * 4;
            uint32_t dst = swb + (ph ^ 1) * 2048;
            #pragma unroll
            for (int e = 0; e < 4; e++) {
                int src = d_srcs[b2 + e];
                cp16(dst + e * 512, xl + (size_t)src * DIM + c);
            }
            CP_COMMIT();
            CP_WAIT1();
        } else {
            CP_WAIT0();
        }
        #pragma unroll
        for (int e = 0; e < 4; e++) {
            float4 v = grd[ph * 128 + e * 32];
            float d = hred8(leaky_dot(v, xr4, w));
            float a = ex2(d - m0);
            denom += a;
            acc.x += a * v.x;
            acc.y += a * v.y;
            acc.z += a * v.z;
            acc.w += a * v.w;
        }
    }
    for (int j = beg + groups * 4; j < end; j++) {
        uint32_t s0 = d_srcs[j];
        float4 v0 = *(const float4*)(xl + (size_t)s0 * DIM + c);
        float a0 = ex2(hred8(leaky_dot(v0, xr4, w)) - m0);
        denom += a0;
        acc.x += a0 * v0.x;
        acc.y += a0 * v0.y;
        acc.z += a0 * v0.z;
        acc.w += a0 * v0.w;
    }

    float inv = 1.0f / denom;
    float4 bias = *(const float4*)(conv_bias + c);
    float4 ga = *(const float4*)(bn_gamma + c);
    float4 be = *(const float4*)(bn_beta + c);
    float4 mu = *(const float4*)(bn_mean + c);
    float4 va = *(const float4*)(bn_var + c);
    float4 o;
    o.x = fmaxf((acc.x * inv + bias.x - mu.x) * rsqrtf(va.x + BN_EPS) * ga.x + be.x, 0.f);
    o.y = fmaxf((acc.y * inv + bias.y - mu.y) * rsqrtf(va.y + BN_EPS) * ga.y + be.y, 0.f);
    o.z = fmaxf((acc.z * inv + bias.z - mu.z) * rsqrtf(va.z + BN_EPS) * ga.z + be.z, 0.f);
    o.w = fmaxf((acc.w * inv + bias.w - mu.w) * rsqrtf(va.w + BN_EPS) * ga.w + be.w, 0.f);

    if (write_f32) *(float4*)(hout + (size_t)i * DIM + c) = o;
    if (write_bf) {
        __nv_bfloat16 hx = __float2bfloat16(o.x);
        __nv_bfloat16 hy = __float2bfloat16(o.y);
        __nv_bfloat16 hz = __float2bfloat16(o.z);
        __nv_bfloat16 hw = __float2bfloat16(o.w);
        __nv_bfloat162* ph2 = (__nv_bfloat162*)(d_hhi + (size_t)i * DIM + c);
        ph2[0] = __nv_bfloat162(hx, hy);
        ph2[1] = __nv_bfloat162(hz, hw);
        __nv_bfloat162* pl2 = (__nv_bfloat162*)(d_hlo + (size_t)i * DIM + c);
        pl2[0] = __nv_bfloat162(__float2bfloat16(o.x - __bfloat162float(hx)),
                                __float2bfloat16(o.y - __bfloat162float(hy)));
        pl2[1] = __nv_bfloat162(__float2bfloat16(o.z - __bfloat162float(hz)),
                                __float2bfloat16(o.w - __bfloat162float(hw)));
    }
}

// ---------------- mean pool (batch sorted) + MLP 128->64->2 ----------------
__global__ void k_pool_mlp(
    const float* __restrict__ h, const int* __restrict__ batch,
    const float* __restrict__ W1, const float* __restrict__ b1,
    const float* __restrict__ W2, const float* __restrict__ b2,
    float* __restrict__ out)
{
    __shared__ float p[DIM];
    __shared__ float hid[64];
    int g = blockIdx.x;
    int t = threadIdx.x;

    int lo = 0, hi = NODES;
    while (lo < hi) { int mid = (lo + hi) >> 1; if (batch[mid] < g) lo = mid + 1; else hi = mid; }
    int beg = lo;
    hi = NODES;
    while (lo < hi) { int mid = (lo + hi) >> 1; if (batch[mid] < g + 1) lo = mid + 1; else hi = mid; }
    int end = lo;

    float sum = 0.f;
    for (int n = beg; n < end; n++) sum += h[(size_t)n * DIM + t];
    float cnt = (float)(end - beg);
    p[t] = sum / fmaxf(cnt, 1.0f);
    __syncthreads();

    if (t < 64) {
        float a = b1[t];
        #pragma unroll 8
        for (int k = 0; k < DIM; k++) a = fmaf(p[k], W1[k * 64 + t], a);
        hid[t] = fmaxf(a, 0.f);
    }
    __syncthreads();

    if (t < 2) {
        float a = b2[t];
        #pragma unroll 8
        for (int k = 0; k < 64; k++) a = fmaf(hid[k], W2[k * 2 + t], a);
        out[g * 2 + t] = a;
    }
}

// ---------------- launch ----------------
extern "C" void kernel_launch(void* const* d_in, const int* in_sizes, int n_in,
                              void* d_out, int out_size)
{
    const float* x     = (const float*)d_in[0];
    const int*   ei    = (const int*)d_in[1];
    const int*   batch = (const int*)d_in[2];
    const float* Wl    = (const float*)d_in[3];
    const float* bl    = (const float*)d_in[4];
    const float* Wr    = (const float*)d_in[5];
    const float* br    = (const float*)d_in[6];
    const float* att   = (const float*)d_in[7];
    const float* cb    = (const float*)d_in[8];
    const float* bng   = (const float*)d_in[9];
    const float* bnb   = (const float*)d_in[10];
    const float* bnm   = (const float*)d_in[11];
    const float* bnv   = (const float*)d_in[12];
    const float* W1    = (const float*)d_in[13];
    const float* b1    = (const float*)d_in[14];
    const float* W2    = (const float*)d_in[15];
    const float* b2    = (const float*)d_in[16];
    float* out = (float*)d_out;

    float *h0, *xl, *xr;
    __nv_bfloat16 *hhi, *hlo, *whi, *wlo;
    cudaGetSymbolAddress((void**)&h0, d_h0);
    cudaGetSymbolAddress((void**)&xl, d_xl);
    cudaGetSymbolAddress((void**)&xr, d_xr);
    cudaGetSymbolAddress((void**)&hhi, d_hhi);
    cudaGetSymbolAddress((void**)&hlo, d_hlo);
    cudaGetSymbolAddress((void**)&whi, d_whi);
    cudaGetSymbolAddress((void**)&wlo, d_wlo);

    static int init_done = 0;
    static cudaStream_t s2;
    static cudaEvent_t evA, evB;
    if (!init_done) {
        cudaFuncSetAttribute(k_gemm_tc, cudaFuncAttributeMaxDynamicSharedMemorySize, GSMEM);
        cudaFuncSetAttribute(k_gemm_l0, cudaFuncAttributeMaxDynamicSharedMemorySize, GSMEM_L0);
        cudaStreamCreateWithFlags(&s2, cudaStreamNonBlocking);
        cudaEventCreateWithFlags(&evA, cudaEventDisableTiming);
        cudaEventCreateWithFlags(&evB, cudaEventDisableTiming);
        init_done = 1;
    }

    dim3 ggrid(74, 2);

    // fork s2 at t=0: CSR chain concurrent with W-convert + GEMM L0
    cudaEventRecord(evA, 0);
    cudaStreamWaitEvent(s2, evA, 0);
    k_zero<<<(NODES + 255) / 256, 256, 0, s2>>>();                    // #0 (s2)
    k_hist<<<(EDGES + 255) / 256, 256, 0, s2>>>(ei);                  // #1 (s2)
    k_conv_w<<<6, 256>>>(Wl, Wr);                                     // #2 (main)
    k_gemm_l0<<<ggrid, 256, GSMEM_L0>>>(x, whi, wlo, bl, br);         // #3 (main) <-- profiled
    k_scan<<<1, 1024, 0, s2>>>();                                     // #4 (s2)
    k_scatter<<<(EDGES + 255) / 256, 256, 0, s2>>>(ei);               // #5 (s2)
    cudaEventRecord(evB, s2);
    cudaStreamWaitEvent(0, evB, 0);

    for (int l = 0; l < 3; l++) {
        if (l > 0) {
            k_gemm_tc<<<ggrid, 256, GSMEM>>>(
                hhi, hlo,
                whi + (size_t)l * 2 * DIM * DIM, wlo + (size_t)l * 2 * DIM * DIM,
                bl + l * DIM, br + l * DIM);
        }
        k_gat<<<NODES / 8, 256>>>(xl, xr,
                                  att + l * DIM, cb + l * DIM,
                                  bng + l * DIM, bnb + l * DIM,
                                  bnm + l * DIM, bnv + l * DIM,
                                  h0, (l < 2) ? 1 : 0, (l == 2) ? 1 : 0);
    }

    k_pool_mlp<<<GRAPHS, 128>>>(h0, batch, W1, b1, W2, b2, out);
}

// round 17
// speedup vs baseline: 1.0518x; 1.0518x over previous
#include <cuda_runtime.h>
#include <cuda_bf16.h>
#include <cstdint>

#define NODES 40000
#define EDGES 640000
#define DIM 128
#define GRAPHS 512
#define NEG_SLOPE 0.2f
#define BN_EPS 1e-5f
#define LOG2E 1.4426950408889634f

// ---------------- scratch (no allocations allowed) ----------------
__device__ float d_h0[NODES * DIM];
__device__ float d_xl[NODES * DIM];
__device__ float d_xr[NODES * DIM];
__device__ __nv_bfloat16 d_hhi[NODES * DIM];
__device__ __nv_bfloat16 d_hlo[NODES * DIM];
__device__ __nv_bfloat16 d_whi[3 * 2 * DIM * DIM];
__device__ __nv_bfloat16 d_wlo[3 * 2 * DIM * DIM];
__device__ int d_deg[NODES];
__device__ int d_rowptr[NODES + 1];
__device__ int d_cursor[NODES];
__device__ int d_srcs[EDGES];

__device__ __forceinline__ uint32_t smem_u32(const void* p) {
    uint32_t a;
    asm("{ .reg .u64 t; cvta.to.shared.u64 t, %1; cvt.u32.u64 %0, t; }" : "=r"(a) : "l"(p));
    return a;
}
__device__ __forceinline__ void ldsm_x4(uint32_t* r, uint32_t addr) {
    asm volatile("ldmatrix.sync.aligned.m8n8.x4.shared.b16 {%0,%1,%2,%3}, [%4];"
                 : "=r"(r[0]), "=r"(r[1]), "=r"(r[2]), "=r"(r[3]) : "r"(addr));
}
__device__ __forceinline__ void ldsm_x4_t(uint32_t* r, uint32_t addr) {
    asm volatile("ldmatrix.sync.aligned.m8n8.x4.trans.shared.b16 {%0,%1,%2,%3}, [%4];"
                 : "=r"(r[0]), "=r"(r[1]), "=r"(r[2]), "=r"(r[3]) : "r"(addr));
}
__device__ __forceinline__ void mma16816(float* c, const uint32_t* a, const uint32_t* b) {
    asm volatile(
        "mma.sync.aligned.m16n8k16.row.col.f32.bf16.bf16.f32 "
        "{%0,%1,%2,%3}, {%4,%5,%6,%7}, {%8,%9}, {%0,%1,%2,%3};"
        : "+f"(c[0]), "+f"(c[1]), "+f"(c[2]), "+f"(c[3])
        : "r"(a[0]), "r"(a[1]), "r"(a[2]), "r"(a[3]), "r"(b[0]), "r"(b[1]));
}
__device__ __forceinline__ void cp16(uint32_t saddr, const void* gaddr) {
    asm volatile("cp.async.cg.shared.global [%0], [%1], 16;" :: "r"(saddr), "l"(gaddr));
}
#define CP_COMMIT() asm volatile("cp.async.commit_group;" ::: "memory")
#define CP_WAIT0()  asm volatile("cp.async.wait_group 0;" ::: "memory")
#define CP_WAIT1()  asm volatile("cp.async.wait_group 1;" ::: "memory")

// ---------------- small kernels ----------------
__global__ void k_zero() {
    int i = blockIdx.x * blockDim.x + threadIdx.x;
    if (i < NODES) d_deg[i] = 0;
}
__global__ void k_conv_w(const float* __restrict__ Wl, const float* __restrict__ Wr) {
    int b = blockIdx.x;
    int l = b >> 1, m = b & 1;
    const float* W = (m ? Wr : Wl) + (size_t)l * DIM * DIM;
    __nv_bfloat16* oh = d_whi + (size_t)(l * 2 + m) * DIM * DIM;
    __nv_bfloat16* ol = d_wlo + (size_t)(l * 2 + m) * DIM * DIM;
    for (int t = threadIdx.x; t < DIM * DIM; t += blockDim.x) {
        float v = W[t];
        __nv_bfloat16 h = __float2bfloat16(v);
        oh[t] = h;
        ol[t] = __float2bfloat16(v - __bfloat162float(h));
    }
}
__global__ void k_hist(const int* __restrict__ ei) {
    int e = blockIdx.x * blockDim.x + threadIdx.x;
    if (e < EDGES) atomicAdd(&d_deg[ei[EDGES + e]], 1);
}
#define SCAN_CH 40
__global__ void k_scan() {
    __shared__ int ws[32];
    int t = threadIdx.x, lane = t & 31, wid = t >> 5;
    int base = t * SCAN_CH;
    int s = 0;
    #pragma unroll 4
    for (int k = 0; k < SCAN_CH; k++) {
        int idx = base + k;
        if (idx < NODES) s += d_deg[idx];
    }
    int x = s;
    #pragma unroll
    for (int o = 1; o < 32; o <<= 1) {
        int y = __shfl_up_sync(0xffffffffu, x, o);
        if (lane >= o) x += y;
    }
    if (lane == 31) ws[wid] = x;
    __syncthreads();
    if (wid == 0) {
        int sv = ws[lane], sx = sv;
        #pragma unroll
        for (int o = 1; o < 32; o <<= 1) {
            int y = __shfl_up_sync(0xffffffffu, sx, o);
            if (lane >= o) sx += y;
        }
        ws[lane] = sx - sv;
    }
    __syncthreads();
    int run = ws[wid] + x - s;
    #pragma unroll 4
    for (int k = 0; k < SCAN_CH; k++) {
        int idx = base + k;
        if (idx < NODES) {
            int dg = d_deg[idx];
            d_rowptr[idx] = run;
            d_cursor[idx] = run;
            run += dg;
        }
    }
    if (t == 1023) d_rowptr[NODES] = run;
}
__global__ void k_scatter(const int* __restrict__ ei) {
    int e = blockIdx.x * blockDim.x + threadIdx.x;
    if (e < EDGES) {
        int dst = ei[EDGES + e];
        int pos = atomicAdd(&d_cursor[dst], 1);
        d_srcs[pos] = ei[e];
    }
}

// ---------------- persistent HMMA dual GEMM (bf16 inputs; layers 1-2) ----------------
#define SW_HI 0
#define SW_LO 32768
#define SA_BUF 65536
#define ABUF_SZ 32768
#define GSMEM 131072
#define NTILES (NODES / 64)

__global__ __launch_bounds__(256, 1) void k_gemm_tc(
    const __nv_bfloat16* __restrict__ Ahi, const __nv_bfloat16* __restrict__ Alo,
    const __nv_bfloat16* __restrict__ Whi, const __nv_bfloat16* __restrict__ Wlo,
    const float* __restrict__ bl, const float* __restrict__ br)
{
    extern __shared__ char smem[];
    uint32_t sb = smem_u32(smem);
    int tid = threadIdx.x;
    int mat = blockIdx.y;

    const float* bias = mat ? br : bl;
    float* out = mat ? d_xr : d_xl;
    const uint4* ahi4 = (const uint4*)Ahi;
    const uint4* alo4 = (const uint4*)Alo;
    const uint4* wh4 = (const uint4*)(Whi + (size_t)mat * DIM * DIM);
    const uint4* wl4 = (const uint4*)(Wlo + (size_t)mat * DIM * DIM);

    int tb0 = blockIdx.x;
    for (int t = tid; t < 2048; t += 256) {
        int r = t >> 4, c = t & 15;
        uint32_t so = r * 256 + ((c ^ (r & 7)) << 4);
        cp16(sb + SW_HI + so, wh4 + t);
        cp16(sb + SW_LO + so, wl4 + t);
    }
    if (tb0 < NTILES) {
        int row0 = tb0 * 64;
        for (int t = tid; t < 1024; t += 256) {
            int r = t >> 4, c = t & 15;
            uint32_t so = r * 256 + ((c ^ (r & 7)) << 4);
            cp16(sb + SA_BUF + so, ahi4 + (row0 + r) * 16 + c);
            cp16(sb + SA_BUF + 16384 + so, alo4 + (row0 + r) * 16 + c);
        }
    }
    CP_COMMIT();
    CP_WAIT0();
    __syncthreads();

    int w = tid >> 5, lane = tid & 31;
    int mBase = (w >> 2) * 32;
    int nBase = (w & 3) * 32;
    int arow = lane & 15;
    int asel = lane >> 4;
    int brow_in = (lane & 7) + ((lane >> 3) & 1) * 8;
    int bsel = lane >> 4;
    int r0 = lane >> 2;
    int c2 = (lane & 3) * 2;

    int buf = 0;
    for (int tb = tb0; tb < NTILES; tb += gridDim.x) {
        int tn = tb + gridDim.x;
        if (tn < NTILES) {
            uint32_t ab = sb + SA_BUF + (buf ^ 1) * ABUF_SZ;
            int rown = tn * 64;
            for (int t = tid; t < 1024; t += 256) {
                int r = t >> 4, c = t & 15;
                uint32_t so = r * 256 + ((c ^ (r & 7)) << 4);
                cp16(ab + so, ahi4 + (rown + r) * 16 + c);
                cp16(ab + 16384 + so, alo4 + (rown + r) * 16 + c);
            }
        }
        CP_COMMIT();

        uint32_t sa_hi = sb + SA_BUF + buf * ABUF_SZ;
        uint32_t sa_lo = sa_hi + 16384;

        float acc[2][4][4];
        #pragma unroll
        for (int mt = 0; mt < 2; mt++)
            #pragma unroll
            for (int nt = 0; nt < 4; nt++)
                #pragma unroll
                for (int j = 0; j < 4; j++) acc[mt][nt][j] = 0.f;

        #pragma unroll
        for (int ks = 0; ks < 8; ks++) {
            uint32_t ah[2][4], al[2][4];
            int achunk = ks * 2 + asel;
            #pragma unroll
            for (int mt = 0; mt < 2; mt++) {
                int r = mBase + mt * 16 + arow;
                uint32_t off = r * 256 + ((achunk ^ (r & 7)) << 4);
                ldsm_x4(ah[mt], sa_hi + off);
                ldsm_x4(al[mt], sa_lo + off);
            }
            uint32_t bh[2][4], bo[2][4];
            int brow = ks * 16 + brow_in;
            #pragma unroll
            for (int nt2 = 0; nt2 < 2; nt2++) {
                int chunk = ((nBase + nt2 * 16) >> 3) + bsel;
                uint32_t off = brow * 256 + ((chunk ^ (brow & 7)) << 4);
                ldsm_x4_t(bh[nt2], sb + SW_HI + off);
                ldsm_x4_t(bo[nt2], sb + SW_LO + off);
            }
            #pragma unroll
            for (int mt = 0; mt < 2; mt++)
                #pragma unroll
                for (int nt = 0; nt < 4; nt++) {
                    const uint32_t* ph = &bh[nt >> 1][(nt & 1) * 2];
                    const uint32_t* pl = &bo[nt >> 1][(nt & 1) * 2];
                    mma16816(acc[mt][nt], ah[mt], ph);
                    mma16816(acc[mt][nt], al[mt], ph);
                    mma16816(acc[mt][nt], ah[mt], pl);
                }
        }

        int row0 = tb * 64;
        #pragma unroll
        for (int nt = 0; nt < 4; nt++) {
            int col = nBase + nt * 8 + c2;
            float2 bi = *(const float2*)(bias + col);
            #pragma unroll
            for (int mt = 0; mt < 2; mt++) {
                int g0 = row0 + mBase + mt * 16 + r0;
                float2 o0 = {acc[mt][nt][0] + bi.x, acc[mt][nt][1] + bi.y};
                *(float2*)(out + (size_t)g0 * DIM + col) = o0;
                float2 o1 = {acc[mt][nt][2] + bi.x, acc[mt][nt][3] + bi.y};
                *(float2*)(out + (size_t)(g0 + 8) * DIM + col) = o1;
            }
        }

        CP_WAIT0();
        __syncthreads();
        buf ^= 1;
    }
}

// ---------------- layer-0 GEMM: fp32 x via cp.async pipeline, convert in smem ----------------
#define L0_F32 65536        // 2 x 32768 fp32 A tile
#define L0_BH 131072        // 16384 bf16 hi
#define L0_BL 147456        // 16384 bf16 lo
#define GSMEM_L0 163840

__global__ __launch_bounds__(256, 1) void k_gemm_l0(
    const float* __restrict__ X,
    const __nv_bfloat16* __restrict__ Whi, const __nv_bfloat16* __restrict__ Wlo,
    const float* __restrict__ bl, const float* __restrict__ br)
{
    extern __shared__ char smem[];
    uint32_t sb = smem_u32(smem);
    int tid = threadIdx.x;
    int mat = blockIdx.y;

    const float* bias = mat ? br : bl;
    float* out = mat ? d_xr : d_xl;
    const uint4* wh4 = (const uint4*)(Whi + (size_t)mat * DIM * DIM);
    const uint4* wl4 = (const uint4*)(Wlo + (size_t)mat * DIM * DIM);

    for (int t = tid; t < 2048; t += 256) {
        int r = t >> 4, c = t & 15;
        uint32_t so = r * 256 + ((c ^ (r & 7)) << 4);
        cp16(sb + SW_HI + so, wh4 + t);
        cp16(sb + SW_LO + so, wl4 + t);
    }
    CP_COMMIT();
    int tb0 = blockIdx.x;
    {
        int row0 = tb0 * 64;
        for (int t2 = tid; t2 < 2048; t2 += 256) {
            int r = t2 >> 5, k = t2 & 31;
            cp16(sb + L0_F32 + r * 512 + k * 16, X + (size_t)(row0 + r) * DIM + k * 4);
        }
    }
    CP_COMMIT();

    int w = tid >> 5, lane = tid & 31;
    int mBase = (w >> 2) * 32;
    int nBase = (w & 3) * 32;
    int arow = lane & 15;
    int asel = lane >> 4;
    int brow_in = (lane & 7) + ((lane >> 3) & 1) * 8;
    int bsel = lane >> 4;
    int r0 = lane >> 2;
    int c2 = (lane & 3) * 2;

    int buf = 0;
    for (int tb = tb0; tb < NTILES; tb += gridDim.x) {
        int tn = tb + gridDim.x;
        if (tn < NTILES) {
            int rown = tn * 64;
            uint32_t fb = sb + L0_F32 + (buf ^ 1) * 32768;
            for (int t2 = tid; t2 < 2048; t2 += 256) {
                int r = t2 >> 5, k = t2 & 31;
                cp16(fb + r * 512 + k * 16, X + (size_t)(rown + r) * DIM + k * 4);
            }
            CP_COMMIT();
            CP_WAIT1();
        } else {
            CP_WAIT0();
        }
        __syncthreads();

        const char* f32b = smem + L0_F32 + buf * 32768;
        for (int t = tid; t < 1024; t += 256) {
            int r = t >> 4, c = t & 15;
            float4 f0 = *(const float4*)(f32b + r * 512 + c * 32);
            float4 f1 = *(const float4*)(f32b + r * 512 + c * 32 + 16);
            __nv_bfloat16 h0 = __float2bfloat16(f0.x), h1 = __float2bfloat16(f0.y);
            __nv_bfloat16 h2 = __float2bfloat16(f0.z), h3 = __float2bfloat16(f0.w);
            __nv_bfloat16 h4 = __float2bfloat16(f1.x), h5 = __float2bfloat16(f1.y);
            __nv_bfloat16 h6 = __float2bfloat16(f1.z), h7 = __float2bfloat16(f1.w);
            __nv_bfloat162 hi[4] = {
                __nv_bfloat162(h0, h1), __nv_bfloat162(h2, h3),
                __nv_bfloat162(h4, h5), __nv_bfloat162(h6, h7)};
            __nv_bfloat162 lo[4] = {
                __nv_bfloat162(__float2bfloat16(f0.x - __bfloat162float(h0)),
                               __float2bfloat16(f0.y - __bfloat162float(h1))),
                __nv_bfloat162(__float2bfloat16(f0.z - __bfloat162float(h2)),
                               __float2bfloat16(f0.w - __bfloat162float(h3))),
                __nv_bfloat162(__float2bfloat16(f1.x - __bfloat162float(h4)),
                               __float2bfloat16(f1.y - __bfloat162float(h5))),
                __nv_bfloat162(__float2bfloat16(f1.z - __bfloat162float(h6)),
                               __float2bfloat16(f1.w - __bfloat162float(h7)))};
            uint32_t so = r * 256 + ((c ^ (r & 7)) << 4);
            *(uint4*)(smem + L0_BH + so) = *(uint4*)hi;
            *(uint4*)(smem + L0_BL + so) = *(uint4*)lo;
        }
        __syncthreads();

        float acc[2][4][4];
        #pragma unroll
        for (int mt = 0; mt < 2; mt++)
            #pragma unroll
            for (int nt = 0; nt < 4; nt++)
                #pragma unroll
                for (int j = 0; j < 4; j++) acc[mt][nt][j] = 0.f;

        #pragma unroll
        for (int ks = 0; ks < 8; ks++) {
            uint32_t ah[2][4], al[2][4];
            int achunk = ks * 2 + asel;
            #pragma unroll
            for (int mt = 0; mt < 2; mt++) {
                int r = mBase + mt * 16 + arow;
                uint32_t off = r * 256 + ((achunk ^ (r & 7)) << 4);
                ldsm_x4(ah[mt], sb + L0_BH + off);
                ldsm_x4(al[mt], sb + L0_BL + off);
            }
            uint32_t bh[2][4], bo[2][4];
            int brow = ks * 16 + brow_in;
            #pragma unroll
            for (int nt2 = 0; nt2 < 2; nt2++) {
                int chunk = ((nBase + nt2 * 16) >> 3) + bsel;
                uint32_t off = brow * 256 + ((chunk ^ (brow & 7)) << 4);
                ldsm_x4_t(bh[nt2], sb + SW_HI + off);
                ldsm_x4_t(bo[nt2], sb + SW_LO + off);
            }
            #pragma unroll
            for (int mt = 0; mt < 2; mt++)
                #pragma unroll
                for (int nt = 0; nt < 4; nt++) {
                    const uint32_t* ph = &bh[nt >> 1][(nt & 1) * 2];
                    const uint32_t* pl = &bo[nt >> 1][(nt & 1) * 2];
                    mma16816(acc[mt][nt], ah[mt], ph);
                    mma16816(acc[mt][nt], al[mt], ph);
                    mma16816(acc[mt][nt], ah[mt], pl);
                }
        }

        int row0 = tb * 64;
        #pragma unroll
        for (int nt = 0; nt < 4; nt++) {
            int col = nBase + nt * 8 + c2;
            float2 bi = *(const float2*)(bias + col);
            #pragma unroll
            for (int mt = 0; mt < 2; mt++) {
                int g0 = row0 + mBase + mt * 16 + r0;
                float2 o0 = {acc[mt][nt][0] + bi.x, acc[mt][nt][1] + bi.y};
                *(float2*)(out + (size_t)g0 * DIM + col) = o0;
                float2 o1 = {acc[mt][nt][2] + bi.x, acc[mt][nt][3] + bi.y};
                *(float2*)(out + (size_t)(g0 + 8) * DIM + col) = o1;
            }
        }
        buf ^= 1;
    }
}

// ---------------- GATv2 aggregation (R15-exact: plain loads, ex2) ----------------
__device__ __forceinline__ float leaky_dot(float4 v, float4 x, float4 w) {
    float zx = v.x + x.x, zy = v.y + x.y, zz = v.z + x.z, zw = v.w + x.w;
    zx = fmaxf(zx, NEG_SLOPE * zx);
    zy = fmaxf(zy, NEG_SLOPE * zy);
    zz = fmaxf(zz, NEG_SLOPE * zz);
    zw = fmaxf(zw, NEG_SLOPE * zw);
    return zx * w.x + zy * w.y + zz * w.z + zw * w.w;
}
__device__ __forceinline__ float hred8(float d) {
    d += __shfl_xor_sync(0xffffffffu, d, 1);
    d += __shfl_xor_sync(0xffffffffu, d, 2);
    d += __shfl_xor_sync(0xffffffffu, d, 4);
    return d;
}
__device__ __forceinline__ float ex2(float x) {
    float r;
    asm("ex2.approx.f32 %0, %1;" : "=f"(r) : "f"(x));
    return r;
}

__global__ __launch_bounds__(256) void k_gat(
    const float* __restrict__ xl, const float* __restrict__ xr,
    const float* __restrict__ att, const float* __restrict__ conv_bias,
    const float* __restrict__ bn_gamma, const float* __restrict__ bn_beta,
    const float* __restrict__ bn_mean, const float* __restrict__ bn_var,
    float* __restrict__ hout, int write_bf, int write_f32)
{
    int i = blockIdx.x * 8 + (threadIdx.x >> 5);
    if (i >= NODES) return;
    int lane = threadIdx.x & 31;
    int c = lane * 4;

    float4 w = *(const float4*)(att + c);
    w.x *= LOG2E; w.y *= LOG2E; w.z *= LOG2E; w.w *= LOG2E;
    float4 xr4 = *(const float4*)(xr + (size_t)i * DIM + c);

    float4 xls = *(const float4*)(xl + (size_t)i * DIM + c);
    float m0 = hred8(leaky_dot(xls, xr4, w));
    float denom = 1.0f;
    float4 acc = xls;

    int beg = d_rowptr[i];
    int end = d_rowptr[i + 1];
    int j = beg;
    for (; j + 4 <= end; j += 4) {
        uint32_t s0 = d_srcs[j];
        uint32_t s1 = d_srcs[j + 1];
        uint32_t s2 = d_srcs[j + 2];
        uint32_t s3 = d_srcs[j + 3];
        float4 v0 = *(const float4*)(xl + (size_t)s0 * DIM + c);
        float4 v1 = *(const float4*)(xl + (size_t)s1 * DIM + c);
        float4 v2 = *(const float4*)(xl + (size_t)s2 * DIM + c);
        float4 v3 = *(const float4*)(xl + (size_t)s3 * DIM + c);
        float d0 = hred8(leaky_dot(v0, xr4, w));
        float d1 = hred8(leaky_dot(v1, xr4, w));
        float d2 = hred8(leaky_dot(v2, xr4, w));
        float d3 = hred8(leaky_dot(v3, xr4, w));
        float a0 = ex2(d0 - m0);
        float a1 = ex2(d1 - m0);
        float a2 = ex2(d2 - m0);
        float a3 = ex2(d3 - m0);
        denom += (a0 + a1) + (a2 + a3);
        acc.x += (a0 * v0.x + a1 * v1.x) + (a2 * v2.x + a3 * v3.x);
        acc.y += (a0 * v0.y + a1 * v1.y) + (a2 * v2.y + a3 * v3.y);
        acc.z += (a0 * v0.z + a1 * v1.z) + (a2 * v2.z + a3 * v3.z);
        acc.w += (a0 * v0.w + a1 * v1.w) + (a2 * v2.w + a3 * v3.w);
    }
    for (; j < end; j++) {
        uint32_t s0 = d_srcs[j];
        float4 v0 = *(const float4*)(xl + (size_t)s0 * DIM + c);
        float a0 = ex2(hred8(leaky_dot(v0, xr4, w)) - m0);
        denom += a0;
        acc.x += a0 * v0.x;
        acc.y += a0 * v0.y;
        acc.z += a0 * v0.z;
        acc.w += a0 * v0.w;
    }

    float inv = 1.0f / denom;
    float4 bias = *(const float4*)(conv_bias + c);
    float4 ga = *(const float4*)(bn_gamma + c);
    float4 be = *(const float4*)(bn_beta + c);
    float4 mu = *(const float4*)(bn_mean + c);
    float4 va = *(const float4*)(bn_var + c);
    float4 o;
    o.x = fmaxf((acc.x * inv + bias.x - mu.x) * rsqrtf(va.x + BN_EPS) * ga.x + be.x, 0.f);
    o.y = fmaxf((acc.y * inv + bias.y - mu.y) * rsqrtf(va.y + BN_EPS) * ga.y + be.y, 0.f);
    o.z = fmaxf((acc.z * inv + bias.z - mu.z) * rsqrtf(va.z + BN_EPS) * ga.z + be.z, 0.f);
    o.w = fmaxf((acc.w * inv + bias.w - mu.w) * rsqrtf(va.w + BN_EPS) * ga.w + be.w, 0.f);

    if (write_f32) *(float4*)(hout + (size_t)i * DIM + c) = o;
    if (write_bf) {
        __nv_bfloat16 hx = __float2bfloat16(o.x);
        __nv_bfloat16 hy = __float2bfloat16(o.y);
        __nv_bfloat16 hz = __float2bfloat16(o.z);
        __nv_bfloat16 hw = __float2bfloat16(o.w);
        __nv_bfloat162* ph = (__nv_bfloat162*)(d_hhi + (size_t)i * DIM + c);
        ph[0] = __nv_bfloat162(hx, hy);
        ph[1] = __nv_bfloat162(hz, hw);
        __nv_bfloat162* pl = (__nv_bfloat162*)(d_hlo + (size_t)i * DIM + c);
        pl[0] = __nv_bfloat162(__float2bfloat16(o.x - __bfloat162float(hx)),
                               __float2bfloat16(o.y - __bfloat162float(hy)));
        pl[1] = __nv_bfloat162(__float2bfloat16(o.z - __bfloat162float(hz)),
                               __float2bfloat16(o.w - __bfloat162float(hw)));
    }
}

// ---------------- mean pool (batch sorted) + MLP 128->64->2 ----------------
__global__ void k_pool_mlp(
    const float* __restrict__ h, const int* __restrict__ batch,
    const float* __restrict__ W1, const float* __restrict__ b1,
    const float* __restrict__ W2, const float* __restrict__ b2,
    float* __restrict__ out)
{
    __shared__ float p[DIM];
    __shared__ float hid[64];
    int g = blockIdx.x;
    int t = threadIdx.x;

    int lo = 0, hi = NODES;
    while (lo < hi) { int mid = (lo + hi) >> 1; if (batch[mid] < g) lo = mid + 1; else hi = mid; }
    int beg = lo;
    hi = NODES;
    while (lo < hi) { int mid = (lo + hi) >> 1; if (batch[mid] < g + 1) lo = mid + 1; else hi = mid; }
    int end = lo;

    float sum = 0.f;
    for (int n = beg; n < end; n++) sum += h[(size_t)n * DIM + t];
    float cnt = (float)(end - beg);
    p[t] = sum / fmaxf(cnt, 1.0f);
    __syncthreads();

    if (t < 64) {
        float a = b1[t];
        #pragma unroll 8
        for (int k = 0; k < DIM; k++) a = fmaf(p[k], W1[k * 64 + t], a);
        hid[t] = fmaxf(a, 0.f);
    }
    __syncthreads();

    if (t < 2) {
        float a = b2[t];
        #pragma unroll 8
        for (int k = 0; k < 64; k++) a = fmaf(hid[k], W2[k * 2 + t], a);
        out[g * 2 + t] = a;
    }
}

// ---------------- launch ----------------
extern "C" void kernel_launch(void* const* d_in, const int* in_sizes, int n_in,
                              void* d_out, int out_size)
{
    const float* x     = (const float*)d_in[0];
    const int*   ei    = (const int*)d_in[1];
    const int*   batch = (const int*)d_in[2];
    const float* Wl    = (const float*)d_in[3];
    const float* bl    = (const float*)d_in[4];
    const float* Wr    = (const float*)d_in[5];
    const float* br    = (const float*)d_in[6];
    const float* att   = (const float*)d_in[7];
    const float* cb    = (const float*)d_in[8];
    const float* bng   = (const float*)d_in[9];
    const float* bnb   = (const float*)d_in[10];
    const float* bnm   = (const float*)d_in[11];
    const float* bnv   = (const float*)d_in[12];
    const float* W1    = (const float*)d_in[13];
    const float* b1    = (const float*)d_in[14];
    const float* W2    = (const float*)d_in[15];
    const float* b2    = (const float*)d_in[16];
    float* out = (float*)d_out;

    float *h0, *xl, *xr;
    __nv_bfloat16 *hhi, *hlo, *whi, *wlo;
    cudaGetSymbolAddress((void**)&h0, d_h0);
    cudaGetSymbolAddress((void**)&xl, d_xl);
    cudaGetSymbolAddress((void**)&xr, d_xr);
    cudaGetSymbolAddress((void**)&hhi, d_hhi);
    cudaGetSymbolAddress((void**)&hlo, d_hlo);
    cudaGetSymbolAddress((void**)&whi, d_whi);
    cudaGetSymbolAddress((void**)&wlo, d_wlo);

    static int init_done = 0;
    static cudaStream_t s2;
    static cudaEvent_t evA, evB;
    if (!init_done) {
        cudaFuncSetAttribute(k_gemm_tc, cudaFuncAttributeMaxDynamicSharedMemorySize, GSMEM);
        cudaFuncSetAttribute(k_gemm_l0, cudaFuncAttributeMaxDynamicSharedMemorySize, GSMEM_L0);
        cudaStreamCreateWithFlags(&s2, cudaStreamNonBlocking);
        cudaEventCreateWithFlags(&evA, cudaEventDisableTiming);
        cudaEventCreateWithFlags(&evB, cudaEventDisableTiming);
        init_done = 1;
    }

    dim3 ggrid(74, 2);

    // fork s2 at t=0: CSR chain concurrent with W-convert + GEMM L0
    cudaEventRecord(evA, 0);
    cudaStreamWaitEvent(s2, evA, 0);
    k_zero<<<(NODES + 255) / 256, 256, 0, s2>>>();                    // #0 (s2)
    k_hist<<<(EDGES + 255) / 256, 256, 0, s2>>>(ei);                  // #1 (s2)
    k_conv_w<<<6, 256>>>(Wl, Wr);                                     // #2 (main)
    k_gemm_l0<<<ggrid, 256, GSMEM_L0>>>(x, whi, wlo, bl, br);         // #3 (main) <-- profiled
    k_scan<<<1, 1024, 0, s2>>>();                                     // #4 (s2)
    k_scatter<<<(EDGES + 255) / 256, 256, 0, s2>>>(ei);               // #5 (s2)
    cudaEventRecord(evB, s2);
    cudaStreamWaitEvent(0, evB, 0);

    for (int l = 0; l < 3; l++) {
        if (l > 0) {
            k_gemm_tc<<<ggrid, 256, GSMEM>>>(
                hhi, hlo,
                whi + (size_t)l * 2 * DIM * DIM, wlo + (size_t)l * 2 * DIM * DIM,
                bl + l * DIM, br + l * DIM);
        }
        k_gat<<<NODES / 8, 256>>>(xl, xr,
                                  att + l * DIM, cb + l * DIM,
                                  bng + l * DIM, bnb + l * DIM,
                                  bnm + l * DIM, bnv + l * DIM,
                                  h0, (l < 2) ? 1 : 0, (l == 2) ? 1 : 0);
    }

    k_pool_mlp<<<GRAPHS, 128>>>(h0, batch, W1, b1, W2, b2, out);
}